// round 9
// baseline (speedup 1.0000x reference)
#include <cuda_runtime.h>
#include <cstdint>
#include <mma.h>
#include <math.h>

using namespace nvcuda;

#define NTOK 8192
#define DIM  384
#define NEXP 8
#define HID  1536
#define OUTD 384
#define NPAIR (NTOK * 2)

#define BM 128
#define BN 128
#define KC 32
#define NSTAGE 3
#define NTHR 512

#define LDA 40    // KC+8 pad (160B rows)
#define LDB 136   // BN+8 pad (544B rows)
#define LDO 136

#define SA_SZ (BM * LDA)            // 5120 floats
#define SB_SZ (KC * LDB)            // 4352 floats
#define STAGE_SZ (SA_SZ + SB_SZ)    // 9472 floats
#define DSM_FLOATS (NSTAGE * STAGE_SZ)   // 28416 floats (sOut 128*136=17408 fits)
#define DSM_BYTES (DSM_FLOATS * 4 + 512) // + sEntry

// ---------------- device scratch ----------------
__device__ int    g_counts[NEXP];
__device__ int    g_list[NEXP * NTOK];
__device__ float2 g_gates[NTOK];
__device__ float  g_x [(size_t)NTOK * DIM];
__device__ float  g_w1[(size_t)NEXP * DIM * HID];
__device__ float  g_w2[(size_t)NEXP * HID * OUTD];
__device__ float  g_h [(size_t)NPAIR * HID];

// ---------------- helpers ----------------
__device__ __forceinline__ void cp16(unsigned smem_dst, const void* gsrc, int srcsize) {
    asm volatile("cp.async.cg.shared.global [%0], [%1], 16, %2;\n"
                 :: "r"(smem_dst), "l"(gsrc), "r"(srcsize) : "memory");
}
__device__ __forceinline__ void cp_commit() {
    asm volatile("cp.async.commit_group;\n" ::: "memory");
}
template<int N>
__device__ __forceinline__ void cp_wait() {
    asm volatile("cp.async.wait_group %0;\n" :: "n"(N) : "memory");
}

// ---------------- small kernels ----------------
__global__ void zero_counts_kernel() {
    if (threadIdx.x < NEXP) g_counts[threadIdx.x] = 0;
}

__global__ void zero_out_kernel(float* __restrict__ out) {
    int i = blockIdx.x * blockDim.x + threadIdx.x;
    if (i < NTOK * OUTD) out[i] = 0.f;
}

__global__ void round_tf32_kernel(const float* __restrict__ src,
                                  float* __restrict__ dst, int n4) {
    int i = blockIdx.x * blockDim.x + threadIdx.x;
    if (i >= n4) return;
    float4 v = ((const float4*)src)[i];
    v.x = wmma::__float_to_tf32(v.x);
    v.y = wmma::__float_to_tf32(v.y);
    v.z = wmma::__float_to_tf32(v.z);
    v.w = wmma::__float_to_tf32(v.w);
    ((float4*)dst)[i] = v;
}

__global__ void router_kernel(const float* __restrict__ x,
                              const float* __restrict__ Wg,
                              const float* __restrict__ bg) {
    int warp = (blockIdx.x * blockDim.x + threadIdx.x) >> 5;
    int lane = threadIdx.x & 31;
    if (warp >= NTOK) return;

    const float* xr = x + (size_t)warp * DIM;
    float acc[NEXP];
#pragma unroll
    for (int e = 0; e < NEXP; e++) acc[e] = 0.f;

    for (int d = lane; d < DIM; d += 32) {
        float xv = xr[d];
        const float* wr = Wg + d * NEXP;
#pragma unroll
        for (int e = 0; e < NEXP; e++) acc[e] += xv * wr[e];
    }
#pragma unroll
    for (int e = 0; e < NEXP; e++) {
#pragma unroll
        for (int off = 16; off > 0; off >>= 1)
            acc[e] += __shfl_xor_sync(0xffffffffu, acc[e], off);
    }
    if (lane == 0) {
        float v0 = -1e30f, v1 = -1e30f;
        int   i0 = 0,      i1 = 0;
#pragma unroll
        for (int e = 0; e < NEXP; e++) {
            float v = acc[e] + bg[e];
            if (v > v0)      { v1 = v0; i1 = i0; v0 = v; i0 = e; }
            else if (v > v1) { v1 = v;  i1 = e; }
        }
        float e1 = expf(v1 - v0);
        float inv = 1.0f / (1.0f + e1);
        g_gates[warp] = make_float2(inv, e1 * inv);

        int p0 = atomicAdd(&g_counts[i0], 1);
        g_list[i0 * NTOK + p0] = warp * 2;
        int p1 = atomicAdd(&g_counts[i1], 1);
        g_list[i1 * NTOK + p1] = warp * 2 + 1;
    }
}

// ---------------- 3-stage cp.async tf32 WMMA grouped GEMM (128x128 tile) ----
// G1:  h = gelu(gather(g_x) @ g_w1[e] + b1[e]) -> g_h (tf32-rounded)
// !G1: out[token] += gate * (gather(g_h) @ g_w2[e] + b2[e])  (2 atomic adds)
template<bool G1>
__global__ __launch_bounds__(NTHR)
void gemm_kernel(const float* __restrict__ A,
                 const float* __restrict__ W,
                 const float* __restrict__ bias,
                 float* __restrict__ out) {
    const int e  = blockIdx.z;
    const int M  = g_counts[e];
    const int m0 = blockIdx.x * BM;
    if (m0 >= M) return;
    const int n0 = blockIdx.y * BN;
    constexpr int Kd = G1 ? DIM : HID;
    constexpr int Nd = G1 ? HID : OUTD;
    constexpr int nk = Kd / KC;

    extern __shared__ __align__(16) float dsm[];
    int* sEntry = (int*)(dsm + DSM_FLOATS);

    const int tid = threadIdx.x;
    if (tid < BM) {
        int r = m0 + tid;
        sEntry[tid] = (r < M) ? g_list[e * NTOK + r] : -1;
    }
    __syncthreads();

    const float* We = W + (size_t)e * Kd * Nd;

    // A chunk 128x32: 4 thr/row, 2 float4 each (cols (t&3)*4 and +16)
    const int ar = tid >> 2;
    const int ac = (tid & 3) * 4;
    // B chunk 32x128: 16 thr/row, 2 float4 each (cols (t&15)*4 and +64)
    const int br = tid >> 4;
    const int bc = (tid & 15) * 4;

    const int aentry = sEntry[ar];
    const float* ag = A + (size_t)(aentry < 0 ? 0 : (G1 ? (aentry >> 1) : aentry)) * Kd + ac;
    const int asz = aentry < 0 ? 0 : 16;
    const float* bgp = We + (size_t)br * Nd + n0 + bc;

    unsigned smem_u32 = (unsigned)__cvta_generic_to_shared(dsm);

    auto issue = [&](int kc) {
        unsigned s0 = smem_u32 + (unsigned)((kc % NSTAGE) * (STAGE_SZ * 4));
        const float* ap = ag + kc * KC;
        cp16(s0 + (unsigned)((ar * LDA + ac) * 4),      ap,      asz);
        cp16(s0 + (unsigned)((ar * LDA + ac + 16) * 4), ap + 16, asz);
        unsigned b0 = s0 + (unsigned)(SA_SZ * 4);
        const float* bp = bgp + (size_t)kc * KC * Nd;
        cp16(b0 + (unsigned)((br * LDB + bc) * 4),      bp,      16);
        cp16(b0 + (unsigned)((br * LDB + bc + 64) * 4), bp + 64, 16);
        cp_commit();
    };

    wmma::fragment<wmma::accumulator, 16, 16, 8, float> c[2][2];
#pragma unroll
    for (int i = 0; i < 2; i++)
#pragma unroll
        for (int j = 0; j < 2; j++) wmma::fill_fragment(c[i][j], 0.f);

    const int w  = tid >> 5;            // 16 warps: 4x4
    const int wm = (w & 3) * 32;
    const int wn = (w >> 2) * 32;

#pragma unroll
    for (int kc = 0; kc < NSTAGE; kc++) issue(kc);

    for (int kc = 0; kc < nk; kc++) {
        int rem = nk - kc;
        if (rem >= 3) cp_wait<2>(); else if (rem == 2) cp_wait<1>(); else cp_wait<0>();
        __syncthreads();

        const float* sA = dsm + (kc % NSTAGE) * STAGE_SZ;
        const float* sB = sA + SA_SZ;
#pragma unroll
        for (int ks = 0; ks < KC / 8; ks++) {
            wmma::fragment<wmma::matrix_a, 16, 16, 8, wmma::precision::tf32, wmma::row_major> a[2];
            wmma::fragment<wmma::matrix_b, 16, 16, 8, wmma::precision::tf32, wmma::row_major> b[2];
            wmma::load_matrix_sync(a[0], sA + wm * LDA + ks * 8, LDA);
            wmma::load_matrix_sync(a[1], sA + (wm + 16) * LDA + ks * 8, LDA);
            wmma::load_matrix_sync(b[0], sB + ks * 8 * LDB + wn, LDB);
            wmma::load_matrix_sync(b[1], sB + ks * 8 * LDB + wn + 16, LDB);
#pragma unroll
            for (int i = 0; i < 2; i++)
#pragma unroll
                for (int j = 0; j < 2; j++)
                    wmma::mma_sync(c[i][j], a[i], b[j], c[i][j]);
        }
        __syncthreads();
        if (kc + NSTAGE < nk) issue(kc + NSTAGE);
    }

    // ---- epilogue via smem ----
    float* sOut = dsm;
#pragma unroll
    for (int i = 0; i < 2; i++)
#pragma unroll
        for (int j = 0; j < 2; j++)
            wmma::store_matrix_sync(sOut + (wm + i * 16) * LDO + wn + j * 16,
                                    c[i][j], LDO, wmma::mem_row_major);
    __syncthreads();

    if (G1) {
        const float* be = bias + e * HID + n0;
        // 128 rows x 32 float4 = 4096 groups / 512 thr = 8 iters
        for (int i = tid; i < BM * (BN / 4); i += NTHR) {
            int r = i >> 5, cg = (i & 31) * 4;
            int entry = sEntry[r];
            if (entry >= 0) {
                float4 v;
                float t0 = sOut[r * LDO + cg + 0] + be[cg + 0];
                float t1 = sOut[r * LDO + cg + 1] + be[cg + 1];
                float t2 = sOut[r * LDO + cg + 2] + be[cg + 2];
                float t3 = sOut[r * LDO + cg + 3] + be[cg + 3];
                v.x = wmma::__float_to_tf32(0.5f * t0 * (1.0f + erff(t0 * 0.70710678118654752f)));
                v.y = wmma::__float_to_tf32(0.5f * t1 * (1.0f + erff(t1 * 0.70710678118654752f)));
                v.z = wmma::__float_to_tf32(0.5f * t2 * (1.0f + erff(t2 * 0.70710678118654752f)));
                v.w = wmma::__float_to_tf32(0.5f * t3 * (1.0f + erff(t3 * 0.70710678118654752f)));
                *(float4*)(out + (size_t)entry * HID + n0 + cg) = v;
            }
        }
    } else {
        const float* be = bias + e * OUTD + n0;
        for (int i = tid; i < BM * BN; i += NTHR) {
            int r = i >> 7, cc = i & 127;
            int entry = sEntry[r];
            if (entry >= 0) {
                float v = sOut[r * LDO + cc] + be[cc];
                int tok = entry >> 1;
                float2 gg = g_gates[tok];
                float gate = (entry & 1) ? gg.y : gg.x;
                atomicAdd(out + (size_t)tok * OUTD + n0 + cc, v * gate);
            }
        }
    }
}

// ---------------- launch ----------------
extern "C" void kernel_launch(void* const* d_in, const int* in_sizes, int n_in,
                              void* d_out, int out_size) {
    const float* x  = (const float*)d_in[0];
    const float* Wg = (const float*)d_in[1];
    const float* bg = (const float*)d_in[2];
    const float* W1 = (const float*)d_in[3];
    const float* b1 = (const float*)d_in[4];
    const float* W2 = (const float*)d_in[5];
    const float* b2 = (const float*)d_in[6];
    float* out = (float*)d_out;

    static bool attr_done = false;
    if (!attr_done) {
        cudaFuncSetAttribute(gemm_kernel<true>,
                             cudaFuncAttributeMaxDynamicSharedMemorySize, DSM_BYTES);
        cudaFuncSetAttribute(gemm_kernel<false>,
                             cudaFuncAttributeMaxDynamicSharedMemorySize, DSM_BYTES);
        attr_done = true;
    }

    float *gx, *gw1, *gw2, *gh;
    cudaGetSymbolAddress((void**)&gx,  g_x);
    cudaGetSymbolAddress((void**)&gw1, g_w1);
    cudaGetSymbolAddress((void**)&gw2, g_w2);
    cudaGetSymbolAddress((void**)&gh,  g_h);

    zero_counts_kernel<<<1, 32>>>();
    router_kernel<<<(NTOK * 32) / 256, 256>>>(x, Wg, bg);
    zero_out_kernel<<<(NTOK * OUTD + 255) / 256, 256>>>(out);
    round_tf32_kernel<<<(NTOK * DIM / 4 + 255) / 256, 256>>>(x, gx, NTOK * DIM / 4);
    round_tf32_kernel<<<(NEXP * DIM * HID / 4 + 255) / 256, 256>>>(W1, gw1, NEXP * DIM * HID / 4);
    round_tf32_kernel<<<(NEXP * HID * OUTD / 4 + 255) / 256, 256>>>(W2, gw2, NEXP * HID * OUTD / 4);
    gemm_kernel<true><<<dim3(NTOK / BM, HID / BN, NEXP), NTHR, DSM_BYTES>>>(gx, gw1, b1, gh);
    gemm_kernel<false><<<dim3(NTOK / BM, OUTD / BN, NEXP), NTHR, DSM_BYTES>>>(gh, gw2, b2, out);
}

// round 10
// speedup vs baseline: 1.0308x; 1.0308x over previous
#include <cuda_runtime.h>
#include <cstdint>
#include <mma.h>
#include <math.h>

using namespace nvcuda;

#define NTOK 8192
#define DIM  384
#define NEXP 8
#define HID  1536
#define OUTD 384
#define NPAIR (NTOK * 2)

#define BM 128
#define BN 128
#define KC 32
#define NTHR 256

#define LDA 36    // KC+4 pad (144B rows, stride mod 32 = 4)
#define LDB 132   // BN+4 pad (528B rows, stride mod 32 = 4)
#define LDO 132

#define SA_SZ (BM * LDA)            // 4608 floats
#define SB_SZ (KC * LDB)            // 4224 floats
#define STAGE_SZ (SA_SZ + SB_SZ)    // 8832 floats
#define DSM_FLOATS (2 * STAGE_SZ)   // 17664 floats (sOut 128*132=16896 fits)
#define DSM_BYTES (DSM_FLOATS * 4 + 512)

// ---------------- device scratch ----------------
__device__ int    g_counts[NEXP];
__device__ int    g_list[NEXP * NTOK];
__device__ float2 g_gates[NTOK];
__device__ float  g_x [(size_t)NTOK * DIM];
__device__ float  g_w1[(size_t)NEXP * DIM * HID];
__device__ float  g_w2[(size_t)NEXP * HID * OUTD];
__device__ float  g_h [(size_t)NPAIR * HID];

// ---------------- helpers ----------------
__device__ __forceinline__ void cp16(unsigned smem_dst, const void* gsrc, int srcsize) {
    asm volatile("cp.async.cg.shared.global [%0], [%1], 16, %2;\n"
                 :: "r"(smem_dst), "l"(gsrc), "r"(srcsize) : "memory");
}
__device__ __forceinline__ void cp_commit() {
    asm volatile("cp.async.commit_group;\n" ::: "memory");
}
template<int N>
__device__ __forceinline__ void cp_wait() {
    asm volatile("cp.async.wait_group %0;\n" :: "n"(N) : "memory");
}

// ---------------- small kernels ----------------
__global__ void zero_counts_kernel() {
    if (threadIdx.x < NEXP) g_counts[threadIdx.x] = 0;
}

__global__ void zero_out_kernel(float* __restrict__ out) {
    int i = blockIdx.x * blockDim.x + threadIdx.x;
    if (i < NTOK * OUTD) out[i] = 0.f;
}

__global__ void round_tf32_kernel(const float* __restrict__ src,
                                  float* __restrict__ dst, int n4) {
    int i = blockIdx.x * blockDim.x + threadIdx.x;
    if (i >= n4) return;
    float4 v = ((const float4*)src)[i];
    v.x = wmma::__float_to_tf32(v.x);
    v.y = wmma::__float_to_tf32(v.y);
    v.z = wmma::__float_to_tf32(v.z);
    v.w = wmma::__float_to_tf32(v.w);
    ((float4*)dst)[i] = v;
}

__global__ void router_kernel(const float* __restrict__ x,
                              const float* __restrict__ Wg,
                              const float* __restrict__ bg) {
    int warp = (blockIdx.x * blockDim.x + threadIdx.x) >> 5;
    int lane = threadIdx.x & 31;
    if (warp >= NTOK) return;

    const float* xr = x + (size_t)warp * DIM;
    float acc[NEXP];
#pragma unroll
    for (int e = 0; e < NEXP; e++) acc[e] = 0.f;

    for (int d = lane; d < DIM; d += 32) {
        float xv = xr[d];
        const float* wr = Wg + d * NEXP;
#pragma unroll
        for (int e = 0; e < NEXP; e++) acc[e] += xv * wr[e];
    }
#pragma unroll
    for (int e = 0; e < NEXP; e++) {
#pragma unroll
        for (int off = 16; off > 0; off >>= 1)
            acc[e] += __shfl_xor_sync(0xffffffffu, acc[e], off);
    }
    if (lane == 0) {
        float v0 = -1e30f, v1 = -1e30f;
        int   i0 = 0,      i1 = 0;
#pragma unroll
        for (int e = 0; e < NEXP; e++) {
            float v = acc[e] + bg[e];
            if (v > v0)      { v1 = v0; i1 = i0; v0 = v; i0 = e; }
            else if (v > v1) { v1 = v;  i1 = e; }
        }
        float e1 = expf(v1 - v0);
        float inv = 1.0f / (1.0f + e1);
        g_gates[warp] = make_float2(inv, e1 * inv);

        int p0 = atomicAdd(&g_counts[i0], 1);
        g_list[i0 * NTOK + p0] = warp * 2;
        int p1 = atomicAdd(&g_counts[i1], 1);
        g_list[i1 * NTOK + p1] = warp * 2 + 1;
    }
}

// ---------------- 2-stage cp.async tf32 WMMA grouped GEMM (128x128, 8 warps)
// warp tile 32x64 (c[2][4]) -> better LDS:MMA ratio than 32x32
// G1:  h = gelu(gather(g_x) @ g_w1[e] + b1[e]) -> g_h (tf32-rounded)
// !G1: out[token] += gate * (gather(g_h) @ g_w2[e] + b2[e])  (2 atomic adds)
template<bool G1>
__global__ __launch_bounds__(NTHR, 2)
void gemm_kernel(const float* __restrict__ A,
                 const float* __restrict__ W,
                 const float* __restrict__ bias,
                 float* __restrict__ out) {
    const int e  = blockIdx.z;
    const int M  = g_counts[e];
    const int m0 = blockIdx.x * BM;
    if (m0 >= M) return;
    const int n0 = blockIdx.y * BN;
    constexpr int Kd = G1 ? DIM : HID;
    constexpr int Nd = G1 ? HID : OUTD;
    constexpr int nk = Kd / KC;

    extern __shared__ __align__(16) float dsm[];
    int* sEntry = (int*)(dsm + DSM_FLOATS);

    const int tid = threadIdx.x;
    if (tid < BM) {
        int r = m0 + tid;
        sEntry[tid] = (r < M) ? g_list[e * NTOK + r] : -1;
    }
    __syncthreads();

    const float* We = W + (size_t)e * Kd * Nd;

    // A chunk 128x32: 2 thr/row, each 4 float4 at (t&1)*16 + {0,4,8,12}
    const int ar = tid >> 1;
    const int af = (tid & 1) * 16;
    // B chunk 32x128: 8 thr/row, each 4 float4 at (t&7)*4 + {0,32,64,96}
    const int br = tid >> 3;
    const int bf = (tid & 7) * 4;

    const int aentry = sEntry[ar];
    const float* ag = A + (size_t)(aentry < 0 ? 0 : (G1 ? (aentry >> 1) : aentry)) * Kd + af;
    const int asz = aentry < 0 ? 0 : 16;
    const float* bgp = We + (size_t)br * Nd + n0 + bf;

    unsigned smem_u32 = (unsigned)__cvta_generic_to_shared(dsm);

    auto issue = [&](int kc) {
        unsigned s0 = smem_u32 + (unsigned)((kc & 1) * (STAGE_SZ * 4));
        const float* ap = ag + kc * KC;
#pragma unroll
        for (int i = 0; i < 4; i++)
            cp16(s0 + (unsigned)((ar * LDA + af + i * 4) * 4), ap + i * 4, asz);
        unsigned b0 = s0 + (unsigned)(SA_SZ * 4);
        const float* bp = bgp + (size_t)kc * KC * Nd;
#pragma unroll
        for (int i = 0; i < 4; i++)
            cp16(b0 + (unsigned)((br * LDB + bf + i * 32) * 4), bp + i * 32, 16);
        cp_commit();
    };

    wmma::fragment<wmma::accumulator, 16, 16, 8, float> c[2][4];
#pragma unroll
    for (int i = 0; i < 2; i++)
#pragma unroll
        for (int j = 0; j < 4; j++) wmma::fill_fragment(c[i][j], 0.f);

    const int w  = tid >> 5;            // 8 warps: 4 (m) x 2 (n)
    const int wm = (w & 3) * 32;
    const int wn = (w >> 2) * 64;

    issue(0);
    issue(1);

    for (int kc = 0; kc < nk; kc++) {
        if (kc == nk - 1) cp_wait<0>(); else cp_wait<1>();
        __syncthreads();

        const float* sA = dsm + (kc & 1) * STAGE_SZ;
        const float* sB = sA + SA_SZ;
#pragma unroll
        for (int ks = 0; ks < KC / 8; ks++) {
            wmma::fragment<wmma::matrix_a, 16, 16, 8, wmma::precision::tf32, wmma::row_major> a[2];
            wmma::fragment<wmma::matrix_b, 16, 16, 8, wmma::precision::tf32, wmma::row_major> b[4];
            wmma::load_matrix_sync(a[0], sA + wm * LDA + ks * 8, LDA);
            wmma::load_matrix_sync(a[1], sA + (wm + 16) * LDA + ks * 8, LDA);
#pragma unroll
            for (int j = 0; j < 4; j++)
                wmma::load_matrix_sync(b[j], sB + ks * 8 * LDB + wn + j * 16, LDB);
#pragma unroll
            for (int i = 0; i < 2; i++)
#pragma unroll
                for (int j = 0; j < 4; j++)
                    wmma::mma_sync(c[i][j], a[i], b[j], c[i][j]);
        }
        __syncthreads();
        if (kc + 2 < nk) issue(kc + 2);
    }

    // ---- epilogue via smem ----
    float* sOut = dsm;
#pragma unroll
    for (int i = 0; i < 2; i++)
#pragma unroll
        for (int j = 0; j < 4; j++)
            wmma::store_matrix_sync(sOut + (wm + i * 16) * LDO + wn + j * 16,
                                    c[i][j], LDO, wmma::mem_row_major);
    __syncthreads();

    if (G1) {
        const float* be = bias + e * HID + n0;
        // 128 rows x 32 float4 = 4096 groups / 256 thr = 16 iters
        for (int i = tid; i < BM * (BN / 4); i += NTHR) {
            int r = i >> 5, cg = (i & 31) * 4;
            int entry = sEntry[r];
            if (entry >= 0) {
                float4 v;
                float t0 = sOut[r * LDO + cg + 0] + be[cg + 0];
                float t1 = sOut[r * LDO + cg + 1] + be[cg + 1];
                float t2 = sOut[r * LDO + cg + 2] + be[cg + 2];
                float t3 = sOut[r * LDO + cg + 3] + be[cg + 3];
                v.x = wmma::__float_to_tf32(0.5f * t0 * (1.0f + erff(t0 * 0.70710678118654752f)));
                v.y = wmma::__float_to_tf32(0.5f * t1 * (1.0f + erff(t1 * 0.70710678118654752f)));
                v.z = wmma::__float_to_tf32(0.5f * t2 * (1.0f + erff(t2 * 0.70710678118654752f)));
                v.w = wmma::__float_to_tf32(0.5f * t3 * (1.0f + erff(t3 * 0.70710678118654752f)));
                *(float4*)(out + (size_t)entry * HID + n0 + cg) = v;
            }
        }
    } else {
        const float* be = bias + e * OUTD + n0;
        for (int i = tid; i < BM * BN; i += NTHR) {
            int r = i >> 7, cc = i & 127;
            int entry = sEntry[r];
            if (entry >= 0) {
                float v = sOut[r * LDO + cc] + be[cc];
                int tok = entry >> 1;
                float2 gg = g_gates[tok];
                float gate = (entry & 1) ? gg.y : gg.x;
                atomicAdd(out + (size_t)tok * OUTD + n0 + cc, v * gate);
            }
        }
    }
}

// ---------------- launch ----------------
extern "C" void kernel_launch(void* const* d_in, const int* in_sizes, int n_in,
                              void* d_out, int out_size) {
    const float* x  = (const float*)d_in[0];
    const float* Wg = (const float*)d_in[1];
    const float* bg = (const float*)d_in[2];
    const float* W1 = (const float*)d_in[3];
    const float* b1 = (const float*)d_in[4];
    const float* W2 = (const float*)d_in[5];
    const float* b2 = (const float*)d_in[6];
    float* out = (float*)d_out;

    static bool attr_done = false;
    if (!attr_done) {
        cudaFuncSetAttribute(gemm_kernel<true>,
                             cudaFuncAttributeMaxDynamicSharedMemorySize, DSM_BYTES);
        cudaFuncSetAttribute(gemm_kernel<false>,
                             cudaFuncAttributeMaxDynamicSharedMemorySize, DSM_BYTES);
        attr_done = true;
    }

    float *gx, *gw1, *gw2, *gh;
    cudaGetSymbolAddress((void**)&gx,  g_x);
    cudaGetSymbolAddress((void**)&gw1, g_w1);
    cudaGetSymbolAddress((void**)&gw2, g_w2);
    cudaGetSymbolAddress((void**)&gh,  g_h);

    zero_counts_kernel<<<1, 32>>>();
    router_kernel<<<(NTOK * 32) / 256, 256>>>(x, Wg, bg);
    zero_out_kernel<<<(NTOK * OUTD + 255) / 256, 256>>>(out);
    round_tf32_kernel<<<(NTOK * DIM / 4 + 255) / 256, 256>>>(x, gx, NTOK * DIM / 4);
    round_tf32_kernel<<<(NEXP * DIM * HID / 4 + 255) / 256, 256>>>(W1, gw1, NEXP * DIM * HID / 4);
    round_tf32_kernel<<<(NEXP * HID * OUTD / 4 + 255) / 256, 256>>>(W2, gw2, NEXP * HID * OUTD / 4);
    gemm_kernel<true><<<dim3(NTOK / BM, HID / BN, NEXP), NTHR, DSM_BYTES>>>(gx, gw1, b1, gh);
    gemm_kernel<false><<<dim3(NTOK / BM, OUTD / BN, NEXP), NTHR, DSM_BYTES>>>(gh, gw2, b2, out);
}

// round 11
// speedup vs baseline: 2.4792x; 2.4051x over previous
#include <cuda_runtime.h>
#include <cstdint>
#include <cuda_fp16.h>
#include <mma.h>
#include <math.h>

using namespace nvcuda;

#define NTOK 8192
#define DIM  384
#define NEXP 8
#define HID  1536
#define OUTD 384
#define NPAIR (NTOK * 2)

#define BM 128
#define BN 64
#define KC 64
#define NTHR 256

#define LDA 72   // KC+8 halves (144B rows)
#define LDB 72   // BN+8 halves
#define LDO 68   // epilogue fp32 stride

#define A_STAGE (BM * LDA)              // 9216 halves
#define B_STAGE (KC * LDB)              // 4608 halves
#define STAGE_HALVES (A_STAGE + B_STAGE) // 13824 halves = 27648 B
#define DSM_BYTES (2 * STAGE_HALVES * 2 + 512)  // 55808 B (sOut 128*68*4=34816 fits)

// ---------------- device scratch ----------------
__device__ int     g_counts[NEXP];
__device__ int     g_list[NEXP * NTOK];
__device__ float2  g_gates[NTOK];
__device__ __half  g_x [(size_t)NTOK * DIM];
__device__ __half  g_w1[(size_t)NEXP * DIM * HID];
__device__ __half  g_w2[(size_t)NEXP * HID * OUTD];
__device__ __half  g_h [(size_t)NPAIR * HID];

// ---------------- helpers ----------------
__device__ __forceinline__ void cp16(unsigned smem_dst, const void* gsrc, int srcsize) {
    asm volatile("cp.async.cg.shared.global [%0], [%1], 16, %2;\n"
                 :: "r"(smem_dst), "l"(gsrc), "r"(srcsize) : "memory");
}
__device__ __forceinline__ void cp_commit() {
    asm volatile("cp.async.commit_group;\n" ::: "memory");
}
template<int N>
__device__ __forceinline__ void cp_wait() {
    asm volatile("cp.async.wait_group %0;\n" :: "n"(N) : "memory");
}

// ---------------- small kernels ----------------
__global__ void zero_counts_kernel() {
    if (threadIdx.x < NEXP) g_counts[threadIdx.x] = 0;
}

__global__ void zero_out_kernel(float* __restrict__ out) {
    int i = blockIdx.x * blockDim.x + threadIdx.x;
    if (i < NTOK * OUTD) out[i] = 0.f;
}

__global__ void round_f16_kernel(const float* __restrict__ src,
                                 __half* __restrict__ dst, int n4) {
    int i = blockIdx.x * blockDim.x + threadIdx.x;
    if (i >= n4) return;
    float4 v = ((const float4*)src)[i];
    __half2 h0 = __floats2half2_rn(v.x, v.y);
    __half2 h1 = __floats2half2_rn(v.z, v.w);
    ((__half2*)dst)[2 * i]     = h0;
    ((__half2*)dst)[2 * i + 1] = h1;
}

__global__ void router_kernel(const float* __restrict__ x,
                              const float* __restrict__ Wg,
                              const float* __restrict__ bg) {
    int warp = (blockIdx.x * blockDim.x + threadIdx.x) >> 5;
    int lane = threadIdx.x & 31;
    if (warp >= NTOK) return;

    const float* xr = x + (size_t)warp * DIM;
    float acc[NEXP];
#pragma unroll
    for (int e = 0; e < NEXP; e++) acc[e] = 0.f;

    for (int d = lane; d < DIM; d += 32) {
        float xv = xr[d];
        const float* wr = Wg + d * NEXP;
#pragma unroll
        for (int e = 0; e < NEXP; e++) acc[e] += xv * wr[e];
    }
#pragma unroll
    for (int e = 0; e < NEXP; e++) {
#pragma unroll
        for (int off = 16; off > 0; off >>= 1)
            acc[e] += __shfl_xor_sync(0xffffffffu, acc[e], off);
    }
    if (lane == 0) {
        float v0 = -1e30f, v1 = -1e30f;
        int   i0 = 0,      i1 = 0;
#pragma unroll
        for (int e = 0; e < NEXP; e++) {
            float v = acc[e] + bg[e];
            if (v > v0)      { v1 = v0; i1 = i0; v0 = v; i0 = e; }
            else if (v > v1) { v1 = v;  i1 = e; }
        }
        float e1 = expf(v1 - v0);
        float inv = 1.0f / (1.0f + e1);
        g_gates[warp] = make_float2(inv, e1 * inv);

        int p0 = atomicAdd(&g_counts[i0], 1);
        g_list[i0 * NTOK + p0] = warp * 2;
        int p1 = atomicAdd(&g_counts[i1], 1);
        g_list[i1 * NTOK + p1] = warp * 2 + 1;
    }
}

// ---------------- 2-stage cp.async fp16 WMMA grouped GEMM (128x64, 8 warps)
// fp16 m16n16k16: same 11-bit mantissa as tf32, half the LDS + mma count,
// 2x HMMA rate. fp32 accumulate.
// G1:  h = gelu(gather(g_x) @ g_w1[e] + b1[e]) -> g_h (fp16)
// !G1: out[token] += gate * (gather(g_h) @ g_w2[e] + b2[e])  (2 atomic adds)
template<bool G1>
__global__ __launch_bounds__(NTHR, 3)
void gemm_kernel(const __half* __restrict__ A,
                 const __half* __restrict__ W,
                 const float* __restrict__ bias,
                 void* __restrict__ outv) {
    const int e  = blockIdx.z;
    const int M  = g_counts[e];
    const int m0 = blockIdx.x * BM;
    if (m0 >= M) return;
    const int n0 = blockIdx.y * BN;
    constexpr int Kd = G1 ? DIM : HID;
    constexpr int Nd = G1 ? HID : OUTD;
    constexpr int nk = Kd / KC;

    extern __shared__ __align__(16) __half dsm[];
    int* sEntry = (int*)(dsm + 2 * STAGE_HALVES);

    const int tid = threadIdx.x;
    if (tid < BM) {
        int r = m0 + tid;
        sEntry[tid] = (r < M) ? g_list[e * NTOK + r] : -1;
    }
    __syncthreads();

    const __half* We = W + (size_t)e * Kd * Nd;

    // A chunk 128x64 halves (128B rows): 2 thr/row, 4x16B each
    const int ar = tid >> 1;
    const int ah = (tid & 1) * 32;      // halves
    // B chunk 64x64 halves: 4 thr/row, 2x16B each
    const int br = tid >> 2;
    const int bh = (tid & 3) * 16;      // halves

    const int aentry = sEntry[ar];
    const __half* ag = A + (size_t)(aentry < 0 ? 0 : (G1 ? (aentry >> 1) : aentry)) * Kd + ah;
    const int asz = aentry < 0 ? 0 : 16;
    const __half* bgp = We + (size_t)br * Nd + n0 + bh;

    unsigned smem_u32 = (unsigned)__cvta_generic_to_shared(dsm);

    auto issue = [&](int kc) {
        unsigned s0 = smem_u32 + (unsigned)((kc & 1) * (STAGE_HALVES * 2));
        const __half* ap = ag + kc * KC;
#pragma unroll
        for (int i = 0; i < 4; i++)
            cp16(s0 + (unsigned)((ar * LDA + ah + i * 8) * 2), ap + i * 8, asz);
        unsigned b0 = s0 + (unsigned)(A_STAGE * 2);
        const __half* bp = bgp + (size_t)kc * KC * Nd;
#pragma unroll
        for (int i = 0; i < 2; i++)
            cp16(b0 + (unsigned)((br * LDB + bh + i * 8) * 2), bp + i * 8, 16);
        cp_commit();
    };

    wmma::fragment<wmma::accumulator, 16, 16, 16, float> c[2][2];
#pragma unroll
    for (int i = 0; i < 2; i++)
#pragma unroll
        for (int j = 0; j < 2; j++) wmma::fill_fragment(c[i][j], 0.f);

    const int w  = tid >> 5;            // 8 warps: 4(m) x 2(n), 32x32 tiles
    const int wm = (w & 3) * 32;
    const int wn = (w >> 2) * 32;

    issue(0);
    issue(1);

    for (int kc = 0; kc < nk; kc++) {
        if (kc == nk - 1) cp_wait<0>(); else cp_wait<1>();
        __syncthreads();

        const __half* sA = dsm + (kc & 1) * STAGE_HALVES;
        const __half* sB = sA + A_STAGE;
#pragma unroll
        for (int ks = 0; ks < KC / 16; ks++) {
            wmma::fragment<wmma::matrix_a, 16, 16, 16, __half, wmma::row_major> a[2];
            wmma::fragment<wmma::matrix_b, 16, 16, 16, __half, wmma::row_major> b[2];
            wmma::load_matrix_sync(a[0], sA + wm * LDA + ks * 16, LDA);
            wmma::load_matrix_sync(a[1], sA + (wm + 16) * LDA + ks * 16, LDA);
            wmma::load_matrix_sync(b[0], sB + ks * 16 * LDB + wn, LDB);
            wmma::load_matrix_sync(b[1], sB + ks * 16 * LDB + wn + 16, LDB);
#pragma unroll
            for (int i = 0; i < 2; i++)
#pragma unroll
                for (int j = 0; j < 2; j++)
                    wmma::mma_sync(c[i][j], a[i], b[j], c[i][j]);
        }
        __syncthreads();
        if (kc + 2 < nk) issue(kc + 2);
    }

    // ---- epilogue via smem (fp32 view) ----
    float* sOut = (float*)dsm;
#pragma unroll
    for (int i = 0; i < 2; i++)
#pragma unroll
        for (int j = 0; j < 2; j++)
            wmma::store_matrix_sync(sOut + (wm + i * 16) * LDO + wn + j * 16,
                                    c[i][j], LDO, wmma::mem_row_major);
    __syncthreads();

    if (G1) {
        __half* out = (__half*)outv;
        const float* be = bias + e * HID + n0;
        // 128 rows x 16 quad-groups = 2048 / 256 thr = 8 iters
        for (int i = tid; i < BM * (BN / 4); i += NTHR) {
            int r = i >> 4, cg = (i & 15) * 4;
            int entry = sEntry[r];
            if (entry >= 0) {
                float t0 = sOut[r * LDO + cg + 0] + be[cg + 0];
                float t1 = sOut[r * LDO + cg + 1] + be[cg + 1];
                float t2 = sOut[r * LDO + cg + 2] + be[cg + 2];
                float t3 = sOut[r * LDO + cg + 3] + be[cg + 3];
                t0 = 0.5f * t0 * (1.0f + erff(t0 * 0.70710678118654752f));
                t1 = 0.5f * t1 * (1.0f + erff(t1 * 0.70710678118654752f));
                t2 = 0.5f * t2 * (1.0f + erff(t2 * 0.70710678118654752f));
                t3 = 0.5f * t3 * (1.0f + erff(t3 * 0.70710678118654752f));
                __half2* dst = (__half2*)(out + (size_t)entry * HID + n0 + cg);
                dst[0] = __floats2half2_rn(t0, t1);
                dst[1] = __floats2half2_rn(t2, t3);
            }
        }
    } else {
        float* out = (float*)outv;
        const float* be = bias + e * OUTD + n0;
        for (int i = tid; i < BM * BN; i += NTHR) {
            int r = i >> 6, cc = i & 63;
            int entry = sEntry[r];
            if (entry >= 0) {
                float v = sOut[r * LDO + cc] + be[cc];
                int tok = entry >> 1;
                float2 gg = g_gates[tok];
                float gate = (entry & 1) ? gg.y : gg.x;
                atomicAdd(out + (size_t)tok * OUTD + n0 + cc, v * gate);
            }
        }
    }
}

// ---------------- launch ----------------
extern "C" void kernel_launch(void* const* d_in, const int* in_sizes, int n_in,
                              void* d_out, int out_size) {
    const float* x  = (const float*)d_in[0];
    const float* Wg = (const float*)d_in[1];
    const float* bg = (const float*)d_in[2];
    const float* W1 = (const float*)d_in[3];
    const float* b1 = (const float*)d_in[4];
    const float* W2 = (const float*)d_in[5];
    const float* b2 = (const float*)d_in[6];
    float* out = (float*)d_out;

    static bool attr_done = false;
    if (!attr_done) {
        cudaFuncSetAttribute(gemm_kernel<true>,
                             cudaFuncAttributeMaxDynamicSharedMemorySize, DSM_BYTES);
        cudaFuncSetAttribute(gemm_kernel<false>,
                             cudaFuncAttributeMaxDynamicSharedMemorySize, DSM_BYTES);
        attr_done = true;
    }

    __half *gx, *gw1, *gw2, *gh;
    cudaGetSymbolAddress((void**)&gx,  g_x);
    cudaGetSymbolAddress((void**)&gw1, g_w1);
    cudaGetSymbolAddress((void**)&gw2, g_w2);
    cudaGetSymbolAddress((void**)&gh,  g_h);

    zero_counts_kernel<<<1, 32>>>();
    router_kernel<<<(NTOK * 32) / 256, 256>>>(x, Wg, bg);
    zero_out_kernel<<<(NTOK * OUTD + 255) / 256, 256>>>(out);
    round_f16_kernel<<<(NTOK * DIM / 4 + 255) / 256, 256>>>(x, gx, NTOK * DIM / 4);
    round_f16_kernel<<<(NEXP * DIM * HID / 4 + 255) / 256, 256>>>(W1, gw1, NEXP * DIM * HID / 4);
    round_f16_kernel<<<(NEXP * HID * OUTD / 4 + 255) / 256, 256>>>(W2, gw2, NEXP * HID * OUTD / 4);
    gemm_kernel<true><<<dim3(NTOK / BM, HID / BN, NEXP), NTHR, DSM_BYTES>>>(gx, gw1, b1, gh);
    gemm_kernel<false><<<dim3(NTOK / BM, OUTD / BN, NEXP), NTHR, DSM_BYTES>>>(gh, gw2, b2, out);
}